// round 2
// baseline (speedup 1.0000x reference)
#include <cuda_runtime.h>
#include <math.h>

#define BB 4
#define DM 1024
#define SS 2048
#define HH 16
#define HD 64

// Scratch (device globals: allocation-free per harness rules)
__device__ float g_xT[BB * SS * DM];      // [B,S,D] x + PE, transposed
__device__ float g_q[BB * HH * SS * HD];  // [B,H,S,hd]
__device__ float g_k[BB * HH * SS * HD];
__device__ float g_v[BB * HH * SS * HD];
__device__ float g_att[BB * SS * DM];     // [B,S,D] attention output (concat heads)

// ---------------------------------------------------------------------------
// Kernel 1: x[B,D,S] + PE(D,S) -> xT[B,S,D]  (smem tile transpose, fused PE)
// ---------------------------------------------------------------------------
__global__ void pe_transpose_kernel(const float* __restrict__ x,
                                    float* __restrict__ xT) {
    __shared__ float tile[32][33];
    int b = blockIdx.z;
    int d0 = blockIdx.y * 32, s0 = blockIdx.x * 32;
    int d = d0 + threadIdx.y;
    int s = s0 + threadIdx.x;
    // pe[2i]   = sin(pos * exp(2i * -ln(10000)/D))
    // pe[2i+1] = cos(pos * exp(2i * -ln(10000)/D))
    float denom = expf((float)(d & ~1) * (-9.210340371976184f / (float)DM));
    float ang = (float)s * denom;
    float pe = (d & 1) ? cosf(ang) : sinf(ang);
    tile[threadIdx.y][threadIdx.x] = x[((size_t)b * DM + d) * SS + s] + pe;
    __syncthreads();
    int s2 = s0 + threadIdx.y;
    int d2 = d0 + threadIdx.x;
    xT[((size_t)b * SS + s2) * DM + d2] = tile[threadIdx.x][threadIdx.y];
}

// ---------------------------------------------------------------------------
// Kernel 2: C[M,N] = A[M,K] @ W[N,K]^T + bias,  M=8192, N=K=1024
// 128x128 block tile, BK=8, 256 threads, 8x8 per-thread microtile.
// mode 0: out[b][h][s][dd] (QKV scatter)   mode 1: out[b][n][s] ([B,D,S])
// ---------------------------------------------------------------------------
__global__ __launch_bounds__(256, 2) void sgemm_kernel(
    const float* __restrict__ A, const float* __restrict__ W,
    const float* __restrict__ bias, float* __restrict__ out, int mode) {
    __shared__ float As[8][128];
    __shared__ float Ws[8][128];
    const int tid = threadIdx.x;
    const int mBase = blockIdx.y * 128;
    const int nBase = blockIdx.x * 128;
    const int lrow = tid >> 1;          // 0..127
    const int lk = (tid & 1) * 4;       // 0 or 4
    const int rm = (tid >> 4) * 8;      // row offset of microtile
    const int rn = (tid & 15) * 8;      // col offset of microtile

    float acc[8][8];
#pragma unroll
    for (int i = 0; i < 8; i++)
#pragma unroll
        for (int j = 0; j < 8; j++) acc[i][j] = 0.f;

    const float* Aptr = A + (size_t)(mBase + lrow) * DM + lk;
    const float* Wptr = W + (size_t)(nBase + lrow) * DM + lk;

    for (int kt = 0; kt < DM; kt += 8) {
        float4 a4 = *(const float4*)(Aptr + kt);
        float4 w4 = *(const float4*)(Wptr + kt);
        As[lk + 0][lrow] = a4.x; As[lk + 1][lrow] = a4.y;
        As[lk + 2][lrow] = a4.z; As[lk + 3][lrow] = a4.w;
        Ws[lk + 0][lrow] = w4.x; Ws[lk + 1][lrow] = w4.y;
        Ws[lk + 2][lrow] = w4.z; Ws[lk + 3][lrow] = w4.w;
        __syncthreads();
#pragma unroll
        for (int k = 0; k < 8; k++) {
            float ar[8], br[8];
            *(float4*)&ar[0] = *(const float4*)&As[k][rm];
            *(float4*)&ar[4] = *(const float4*)&As[k][rm + 4];
            *(float4*)&br[0] = *(const float4*)&Ws[k][rn];
            *(float4*)&br[4] = *(const float4*)&Ws[k][rn + 4];
#pragma unroll
            for (int i = 0; i < 8; i++)
#pragma unroll
                for (int j = 0; j < 8; j++)
                    acc[i][j] = fmaf(ar[i], br[j], acc[i][j]);
        }
        __syncthreads();
    }

    if (mode == 0) {
#pragma unroll
        for (int i = 0; i < 8; i++) {
            int m = mBase + rm + i;
            int b = m / SS, s = m % SS;
#pragma unroll
            for (int jj = 0; jj < 8; jj += 4) {
                int n = nBase + rn + jj;
                int h = n / HD, dd = n % HD;
                float4 v4;
                v4.x = acc[i][jj + 0] + bias[n + 0];
                v4.y = acc[i][jj + 1] + bias[n + 1];
                v4.z = acc[i][jj + 2] + bias[n + 2];
                v4.w = acc[i][jj + 3] + bias[n + 3];
                *(float4*)&out[((size_t)(b * HH + h) * SS + s) * HD + dd] = v4;
            }
        }
    } else {
#pragma unroll
        for (int i = 0; i < 8; i++) {
            int m = mBase + rm + i;
            int b = m / SS, s = m % SS;
#pragma unroll
            for (int j = 0; j < 8; j++) {
                int n = nBase + rn + j;
                out[((size_t)b * DM + n) * SS + s] = acc[i][j] + bias[n];
            }
        }
    }
}

// ---------------------------------------------------------------------------
// Kernel 3: flash attention, fp32. One block = (b,h, 64-query tile).
// 64x64 score tiles, 256 threads as 16x16, 4x4 per-thread microtile.
// Online softmax: per-row m/l via 16-lane shfl reductions (replicated).
// ---------------------------------------------------------------------------
#define QPAD 68  // 64 + 4 pad: keeps float4 alignment, kills transposed-store conflicts

__global__ __launch_bounds__(256) void attn_kernel(
    const float* __restrict__ Q, const float* __restrict__ K,
    const float* __restrict__ V, float* __restrict__ O) {
    extern __shared__ float sm[];
    float* Qs = sm;                    // [64 dim][QPAD rows]  (Q^T, scaled)
    float* Ks = Qs + 64 * QPAD;        // [64 dim][QPAD cols]  (K^T)
    float* Ps = Ks + 64 * QPAD;        // [64 col][QPAD rows]  (P^T)
    float* Vs = Ps + 64 * QPAD;        // [64 row][64 dim]

    const int tid = threadIdx.x;
    const int bh = blockIdx.y;
    const int b = bh >> 4, h = bh & 15;
    const int q0 = blockIdx.x * 64;
    const float* Qb = Q + (size_t)bh * SS * HD;
    const float* Kb = K + (size_t)bh * SS * HD;
    const float* Vb = V + (size_t)bh * SS * HD;

    // Load Q tile transposed, pre-scaled by 1/sqrt(64)
#pragma unroll
    for (int i = 0; i < 16; i++) {
        int idx = tid + i * 256;
        int r = idx >> 6, dd = idx & 63;
        Qs[dd * QPAD + r] = Qb[(size_t)(q0 + r) * HD + dd] * 0.125f;
    }

    const int r0 = (tid >> 4) * 4;   // 4 query rows
    const int c0 = (tid & 15) * 4;   // 4 key cols (also 4 V dims)

    float o[4][4];
    float mi[4], li[4];
#pragma unroll
    for (int i = 0; i < 4; i++) {
        mi[i] = -1e30f; li[i] = 0.f;
#pragma unroll
        for (int j = 0; j < 4; j++) o[i][j] = 0.f;
    }

    for (int kt = 0; kt < SS; kt += 64) {
        __syncthreads();  // protect Ks/Vs/Ps reuse (and Qs on first iter)
#pragma unroll
        for (int i = 0; i < 16; i++) {
            int idx = tid + i * 256;
            int r = idx >> 6, dd = idx & 63;
            Ks[dd * QPAD + r] = Kb[(size_t)(kt + r) * HD + dd];
            Vs[r * 64 + dd] = Vb[(size_t)(kt + r) * HD + dd];
        }
        __syncthreads();

        // S = Q^T-tile . K-tile  (scores already scaled via Q)
        float sc[4][4];
#pragma unroll
        for (int i = 0; i < 4; i++)
#pragma unroll
            for (int j = 0; j < 4; j++) sc[i][j] = 0.f;
#pragma unroll
        for (int kk = 0; kk < 64; kk++) {
            float qa[4], ka[4];
            *(float4*)qa = *(const float4*)&Qs[kk * QPAD + r0];
            *(float4*)ka = *(const float4*)&Ks[kk * QPAD + c0];
#pragma unroll
            for (int i = 0; i < 4; i++)
#pragma unroll
                for (int j = 0; j < 4; j++)
                    sc[i][j] = fmaf(qa[i], ka[j], sc[i][j]);
        }

        // Online softmax per row; 16 lanes of a row group compute identically.
#pragma unroll
        for (int i = 0; i < 4; i++) {
            float mx = fmaxf(fmaxf(sc[i][0], sc[i][1]), fmaxf(sc[i][2], sc[i][3]));
#pragma unroll
            for (int off = 8; off >= 1; off >>= 1)
                mx = fmaxf(mx, __shfl_xor_sync(0xffffffffu, mx, off));
            float mn = fmaxf(mi[i], mx);
            float p[4];
            float rsum = 0.f;
#pragma unroll
            for (int j = 0; j < 4; j++) { p[j] = expf(sc[i][j] - mn); rsum += p[j]; }
#pragma unroll
            for (int off = 8; off >= 1; off >>= 1)
                rsum += __shfl_xor_sync(0xffffffffu, rsum, off);
            float f = expf(mi[i] - mn);
            li[i] = li[i] * f + rsum;
            mi[i] = mn;
#pragma unroll
            for (int j = 0; j < 4; j++) o[i][j] *= f;
#pragma unroll
            for (int j = 0; j < 4; j++) Ps[(c0 + j) * QPAD + (r0 + i)] = p[j];
        }
        __syncthreads();  // P visible to all before PV

        // O += P . V
#pragma unroll
        for (int c = 0; c < 64; c++) {
            float pr[4], vr[4];
            *(float4*)pr = *(const float4*)&Ps[c * QPAD + r0];
            *(float4*)vr = *(const float4*)&Vs[c * 64 + c0];
#pragma unroll
            for (int i = 0; i < 4; i++)
#pragma unroll
                for (int j = 0; j < 4; j++)
                    o[i][j] = fmaf(pr[i], vr[j], o[i][j]);
        }
    }

    // Normalize and write [B,S,D] (head h occupies cols h*64..h*64+63)
#pragma unroll
    for (int i = 0; i < 4; i++) {
        float inv = 1.f / li[i];
        float4 v4 = make_float4(o[i][0] * inv, o[i][1] * inv,
                                o[i][2] * inv, o[i][3] * inv);
        *(float4*)&O[((size_t)b * SS + q0 + r0 + i) * DM + h * HD + c0] = v4;
    }
}

// ---------------------------------------------------------------------------
extern "C" void kernel_launch(void* const* d_in, const int* in_sizes, int n_in,
                              void* d_out, int out_size) {
    const float* x  = (const float*)d_in[0];
    const float* Wq = (const float*)d_in[1];
    const float* bq = (const float*)d_in[2];
    const float* Wk = (const float*)d_in[3];
    const float* bk = (const float*)d_in[4];
    const float* Wv = (const float*)d_in[5];
    const float* bv = (const float*)d_in[6];
    const float* Wo = (const float*)d_in[7];
    const float* bo = (const float*)d_in[8];
    // d_in[9] = num_heads (compile-time constant HH=16)

    float *xT, *q, *k, *v, *att;
    cudaGetSymbolAddress((void**)&xT, g_xT);
    cudaGetSymbolAddress((void**)&q, g_q);
    cudaGetSymbolAddress((void**)&k, g_k);
    cudaGetSymbolAddress((void**)&v, g_v);
    cudaGetSymbolAddress((void**)&att, g_att);

    pe_transpose_kernel<<<dim3(SS / 32, DM / 32, BB), dim3(32, 32)>>>(x, xT);

    dim3 gg(DM / 128, (BB * SS) / 128);  // (8, 64)
    sgemm_kernel<<<gg, 256>>>(xT, Wq, bq, q, 0);
    sgemm_kernel<<<gg, 256>>>(xT, Wk, bk, k, 0);
    sgemm_kernel<<<gg, 256>>>(xT, Wv, bv, v, 0);

    int smem = (3 * 64 * QPAD + 64 * 64) * (int)sizeof(float);  // 68608 B
    cudaFuncSetAttribute(attn_kernel,
                         cudaFuncAttributeMaxDynamicSharedMemorySize, smem);
    attn_kernel<<<dim3(SS / 64, BB * HH), 256, smem>>>(q, k, v, att);

    sgemm_kernel<<<gg, 256>>>(att, Wo, bo, (float*)d_out, 1);
}

// round 4
// speedup vs baseline: 1.2828x; 1.2828x over previous
#include <cuda_runtime.h>
#include <cuda_bf16.h>
#include <math.h>
#include <stdint.h>

#define BB 4
#define DM 1024
#define SS 2048
#define HH 16
#define HD 64
#define K3 3072  // tripled K: [interleaved (hi,lo) x2048 | tail x1024]

// ---------------- scratch (device globals; allocation-free) ----------------
__device__ __nv_bfloat16 g_xTbig[(size_t)BB * SS * K3];   // activations, split
__device__ __nv_bfloat16 g_Wqb[(size_t)DM * K3];
__device__ __nv_bfloat16 g_Wkb[(size_t)DM * K3];
__device__ __nv_bfloat16 g_Wvb[(size_t)DM * K3];
__device__ __nv_bfloat16 g_Wob[(size_t)DM * K3];
__device__ float g_q[(size_t)BB * HH * SS * HD];
__device__ float g_k[(size_t)BB * HH * SS * HD];
__device__ float g_v[(size_t)BB * HH * SS * HD];
__device__ __nv_bfloat16 g_attbig[(size_t)BB * SS * K3]; // attention out, split

// ---------------- helpers ----------------
__device__ __forceinline__ uint32_t smem_u32(const void* p) {
    uint32_t a;
    asm("{ .reg .u64 t; cvta.to.shared.u64 t, %1; cvt.u32.u64 %0, t; }" : "=r"(a) : "l"(p));
    return a;
}
__device__ __forceinline__ void cp16(uint32_t s, const void* g) {
    asm volatile("cp.async.cg.shared.global [%0], [%1], 16;" :: "r"(s), "l"(g) : "memory");
}
#define CP_COMMIT() asm volatile("cp.async.commit_group;" ::: "memory")
#define CP_WAIT1()  asm volatile("cp.async.wait_group 1;" ::: "memory")
#define CP_WAIT0()  asm volatile("cp.async.wait_group 0;" ::: "memory")

__device__ __forceinline__ void ldsm4(uint32_t* r, uint32_t addr) {
    asm volatile("ldmatrix.sync.aligned.m8n8.x4.shared.b16 {%0,%1,%2,%3}, [%4];"
                 : "=r"(r[0]), "=r"(r[1]), "=r"(r[2]), "=r"(r[3]) : "r"(addr));
}
__device__ __forceinline__ void mma16816(float* c, const uint32_t* a,
                                         uint32_t b0, uint32_t b1) {
    asm volatile("mma.sync.aligned.m16n8k16.row.col.f32.bf16.bf16.f32 "
                 "{%0,%1,%2,%3}, {%4,%5,%6,%7}, {%8,%9}, {%0,%1,%2,%3};"
                 : "+f"(c[0]), "+f"(c[1]), "+f"(c[2]), "+f"(c[3])
                 : "r"(a[0]), "r"(a[1]), "r"(a[2]), "r"(a[3]), "r"(b0), "r"(b1));
}
__device__ __forceinline__ void split2(float v, __nv_bfloat16& hi, __nv_bfloat16& lo) {
    hi = __float2bfloat16(v);
    lo = __float2bfloat16(v - __bfloat162float(hi));
}
__device__ __forceinline__ uint32_t pack2(__nv_bfloat16 a, __nv_bfloat16 b) {
    return (uint32_t)__bfloat16_as_ushort(a) | ((uint32_t)__bfloat16_as_ushort(b) << 16);
}

// ---------------------------------------------------------------------------
// Kernel 1: x[B,D,S] + PE -> xTbig rows [ (ah,al)x1024 | ah x1024 ]
// ---------------------------------------------------------------------------
__global__ void pe_transpose_split(const float* __restrict__ x,
                                   __nv_bfloat16* __restrict__ out) {
    __shared__ float tile[32][33];
    int b = blockIdx.z;
    int d0 = blockIdx.y * 32, s0 = blockIdx.x * 32;
    int d = d0 + threadIdx.y, s = s0 + threadIdx.x;
    float denom = expf((float)(d & ~1) * (-9.210340371976184f / (float)DM));
    float ang = (float)s * denom;
    float pe = (d & 1) ? cosf(ang) : sinf(ang);
    tile[threadIdx.y][threadIdx.x] = x[((size_t)b * DM + d) * SS + s] + pe;
    __syncthreads();
    int s2 = s0 + threadIdx.y, d2 = d0 + threadIdx.x;
    float v = tile[threadIdx.x][threadIdx.y];
    __nv_bfloat16 hi, lo; split2(v, hi, lo);
    size_t base = ((size_t)b * SS + s2) * K3;
    *(uint32_t*)&out[base + 2 * d2] = pack2(hi, lo);
    out[base + 2048 + d2] = hi;
}

// ---------------------------------------------------------------------------
// Kernel 1b: weight split -> rows [ (wh,wh)x1024 | wl x1024 ]
// ---------------------------------------------------------------------------
__global__ void wsplit_kernel(const float* __restrict__ w0, const float* __restrict__ w1,
                              const float* __restrict__ w2, const float* __restrict__ w3,
                              __nv_bfloat16* o0, __nv_bfloat16* o1,
                              __nv_bfloat16* o2, __nv_bfloat16* o3) {
    const float* src; __nv_bfloat16* dst;
    switch (blockIdx.y) {
        case 0: src = w0; dst = o0; break;
        case 1: src = w1; dst = o1; break;
        case 2: src = w2; dst = o2; break;
        default: src = w3; dst = o3; break;
    }
    int idx = blockIdx.x * 256 + threadIdx.x;  // over DM*DM
    int n = idx >> 10, dcol = idx & 1023;
    __nv_bfloat16 hi, lo; split2(src[idx], hi, lo);
    size_t base = (size_t)n * K3;
    *(uint32_t*)&dst[base + 2 * dcol] = pack2(hi, hi);
    dst[base + 2048 + dcol] = lo;
}

// ---------------------------------------------------------------------------
// Kernel 2: HMMA bf16 GEMM.  C[8192,1024] = A[8192,K3]·W[1024,K3]^T + bias
// 128x128 tile, BK=32, 2-stage cp.async pipeline, 8 warps (4x2), warp tile 32x64.
// Smem tiles padded to 40 bf16/row (80B) -> conflict-free ldmatrix.
// mode 0: scatter fp32 to [B,H,S,hd].  mode 1: scatter fp32 to [B,D,S].
// ---------------------------------------------------------------------------
#define STG 20480           // one stage: A 128x40x2 + W 128x40x2
#define GEMM_SMEM (128 * 129 * 4)  // 66048; stages (40960) overlay this

__global__ __launch_bounds__(256, 2)
void hmma_gemm(const __nv_bfloat16* __restrict__ A, const __nv_bfloat16* __restrict__ W,
               const float* __restrict__ bias, float* __restrict__ out, int mode) {
    extern __shared__ char smem[];
    const uint32_t sb = smem_u32(smem);
    const int tid = threadIdx.x, wid = tid >> 5, lane = tid & 31;
    const int wr = wid >> 1, wc = wid & 1;
    const int mBase = blockIdx.y * 128, nBase = blockIdx.x * 128;

    float acc[2][8][4];
#pragma unroll
    for (int i = 0; i < 2; i++)
#pragma unroll
        for (int j = 0; j < 8; j++)
#pragma unroll
            for (int r = 0; r < 4; r++) acc[i][j][r] = 0.f;

    // loader indices: 512 segs of 16B per tile, 2 per thread (rows r0, r0+64)
    const int r0 = tid >> 2, c4 = tid & 3;
    const __nv_bfloat16* gA = A + (size_t)(mBase + r0) * K3 + c4 * 8;
    const __nv_bfloat16* gW = W + (size_t)(nBase + r0) * K3 + c4 * 8;

#define LOAD_CHUNK(c, st)                                                     \
    do {                                                                      \
        uint32_t sA = sb + (st) * STG + r0 * 80 + c4 * 16;                    \
        uint32_t sW = sA + 10240;                                             \
        cp16(sA, gA + (c) * 32);                                              \
        cp16(sA + 64 * 80, gA + (size_t)64 * K3 + (c) * 32);                  \
        cp16(sW, gW + (c) * 32);                                              \
        cp16(sW + 64 * 80, gW + (size_t)64 * K3 + (c) * 32);                  \
        CP_COMMIT();                                                          \
    } while (0)

    LOAD_CHUNK(0, 0);
    LOAD_CHUNK(1, 1);

    const uint32_t aB = (wr * 32 + (lane & 15)) * 80 + (lane >> 4) * 16;
    const uint32_t bB = 10240 + (wc * 64 + (lane & 15)) * 80 + (lane >> 4) * 16;

    const int NCH = K3 / 32;  // 96
    for (int c = 0; c < NCH; c++) {
        if (c == NCH - 1) CP_WAIT0(); else CP_WAIT1();
        __syncthreads();
        const uint32_t stg = sb + (c & 1) * STG;
#pragma unroll
        for (int ks = 0; ks < 2; ks++) {
            uint32_t a[2][4], b[4][4];
            ldsm4(a[0], stg + aB + ks * 32);
            ldsm4(a[1], stg + aB + 16 * 80 + ks * 32);
#pragma unroll
            for (int j2 = 0; j2 < 4; j2++)
                ldsm4(b[j2], stg + bB + j2 * 16 * 80 + ks * 32);
#pragma unroll
            for (int mi = 0; mi < 2; mi++)
#pragma unroll
                for (int nj = 0; nj < 8; nj++)
                    mma16816(acc[mi][nj], a[mi],
                             b[nj >> 1][nj & 1], b[nj >> 1][(nj & 1) + 2]);
        }
        __syncthreads();
        if (c + 2 < NCH) LOAD_CHUNK(c + 2, c & 1);
    }
#undef LOAD_CHUNK

    // epilogue: acc -> padded smem [128][129] fp32
    __syncthreads();
    float* ep = (float*)smem;
#pragma unroll
    for (int mi = 0; mi < 2; mi++)
#pragma unroll
        for (int nj = 0; nj < 8; nj++) {
            int row = wr * 32 + mi * 16 + (lane >> 2);
            int col = wc * 64 + nj * 8 + (lane & 3) * 2;
            ep[row * 129 + col] = acc[mi][nj][0];
            ep[row * 129 + col + 1] = acc[mi][nj][1];
            ep[(row + 8) * 129 + col] = acc[mi][nj][2];
            ep[(row + 8) * 129 + col + 1] = acc[mi][nj][3];
        }
    __syncthreads();

    if (mode == 0) {
#pragma unroll
        for (int i = 0; i < 8; i++) {
            int r = (tid >> 4) + i * 16;
            int cc = (tid & 15) * 8;
            int m = mBase + r, b = m >> 11, s = m & 2047;
            int n = nBase + cc, h = n >> 6, dd = n & 63;
            float4 v0, v1;
            v0.x = ep[r * 129 + cc + 0] + bias[n + 0];
            v0.y = ep[r * 129 + cc + 1] + bias[n + 1];
            v0.z = ep[r * 129 + cc + 2] + bias[n + 2];
            v0.w = ep[r * 129 + cc + 3] + bias[n + 3];
            v1.x = ep[r * 129 + cc + 4] + bias[n + 4];
            v1.y = ep[r * 129 + cc + 5] + bias[n + 5];
            v1.z = ep[r * 129 + cc + 6] + bias[n + 6];
            v1.w = ep[r * 129 + cc + 7] + bias[n + 7];
            float* dst = out + (((size_t)(b * HH + h) * SS + s) * HD + dd);
            *(float4*)dst = v0;
            *(float4*)(dst + 4) = v1;
        }
    } else {
        int nl = tid >> 1;
        int n = nBase + nl;
        float bn = bias[n];
#pragma unroll
        for (int ii = 0; ii < 16; ii++) {
            int sl = (tid & 1) * 64 + ii * 4;
            int m0 = mBase + sl, b = m0 >> 11, s = m0 & 2047;
            float4 v;
            v.x = ep[(sl + 0) * 129 + nl] + bn;
            v.y = ep[(sl + 1) * 129 + nl] + bn;
            v.z = ep[(sl + 2) * 129 + nl] + bn;
            v.w = ep[(sl + 3) * 129 + nl] + bn;
            *(float4*)&out[((size_t)b * DM + n) * SS + s] = v;
        }
    }
}

// ---------------------------------------------------------------------------
// Kernel 3: flash attention fp32; epilogue emits split layout for Wo GEMM
// ---------------------------------------------------------------------------
#define QPAD 68

__global__ __launch_bounds__(256) void attn_kernel(
    const float* __restrict__ Q, const float* __restrict__ K,
    const float* __restrict__ V, __nv_bfloat16* __restrict__ O) {
    extern __shared__ float sm[];
    float* Qs = sm;
    float* Ks = Qs + 64 * QPAD;
    float* Ps = Ks + 64 * QPAD;
    float* Vs = Ps + 64 * QPAD;

    const int tid = threadIdx.x;
    const int bh = blockIdx.y;
    const int b = bh >> 4, h = bh & 15;
    const int q0 = blockIdx.x * 64;
    const float* Qb = Q + (size_t)bh * SS * HD;
    const float* Kb = K + (size_t)bh * SS * HD;
    const float* Vb = V + (size_t)bh * SS * HD;

#pragma unroll
    for (int i = 0; i < 16; i++) {
        int idx = tid + i * 256;
        int r = idx >> 6, dd = idx & 63;
        Qs[dd * QPAD + r] = Qb[(size_t)(q0 + r) * HD + dd] * 0.125f;
    }

    const int r0 = (tid >> 4) * 4;
    const int c0 = (tid & 15) * 4;

    float o[4][4], mi[4], li[4];
#pragma unroll
    for (int i = 0; i < 4; i++) {
        mi[i] = -1e30f; li[i] = 0.f;
#pragma unroll
        for (int j = 0; j < 4; j++) o[i][j] = 0.f;
    }

    for (int kt = 0; kt < SS; kt += 64) {
        __syncthreads();
#pragma unroll
        for (int i = 0; i < 16; i++) {
            int idx = tid + i * 256;
            int r = idx >> 6, dd = idx & 63;
            Ks[dd * QPAD + r] = Kb[(size_t)(kt + r) * HD + dd];
            Vs[r * 64 + dd] = Vb[(size_t)(kt + r) * HD + dd];
        }
        __syncthreads();

        float sc[4][4];
#pragma unroll
        for (int i = 0; i < 4; i++)
#pragma unroll
            for (int j = 0; j < 4; j++) sc[i][j] = 0.f;
#pragma unroll
        for (int kk = 0; kk < 64; kk++) {
            float qa[4], ka[4];
            *(float4*)qa = *(const float4*)&Qs[kk * QPAD + r0];
            *(float4*)ka = *(const float4*)&Ks[kk * QPAD + c0];
#pragma unroll
            for (int i = 0; i < 4; i++)
#pragma unroll
                for (int j = 0; j < 4; j++)
                    sc[i][j] = fmaf(qa[i], ka[j], sc[i][j]);
        }

#pragma unroll
        for (int i = 0; i < 4; i++) {
            float mx = fmaxf(fmaxf(sc[i][0], sc[i][1]), fmaxf(sc[i][2], sc[i][3]));
#pragma unroll
            for (int off = 8; off >= 1; off >>= 1)
                mx = fmaxf(mx, __shfl_xor_sync(0xffffffffu, mx, off));
            float mn = fmaxf(mi[i], mx);
            float p[4], rsum = 0.f;
#pragma unroll
            for (int j = 0; j < 4; j++) { p[j] = expf(sc[i][j] - mn); rsum += p[j]; }
#pragma unroll
            for (int off = 8; off >= 1; off >>= 1)
                rsum += __shfl_xor_sync(0xffffffffu, rsum, off);
            float f = expf(mi[i] - mn);
            li[i] = li[i] * f + rsum;
            mi[i] = mn;
#pragma unroll
            for (int j = 0; j < 4; j++) o[i][j] *= f;
#pragma unroll
            for (int j = 0; j < 4; j++) Ps[(c0 + j) * QPAD + (r0 + i)] = p[j];
        }
        __syncthreads();

#pragma unroll
        for (int c = 0; c < 64; c++) {
            float pr[4], vr[4];
            *(float4*)pr = *(const float4*)&Ps[c * QPAD + r0];
            *(float4*)vr = *(const float4*)&Vs[c * 64 + c0];
#pragma unroll
            for (int i = 0; i < 4; i++)
#pragma unroll
                for (int j = 0; j < 4; j++)
                    o[i][j] = fmaf(pr[i], vr[j], o[i][j]);
        }
    }

    // write split layout: interleaved (hi,lo) pairs + hi tail
#pragma unroll
    for (int i = 0; i < 4; i++) {
        float inv = 1.f / li[i];
        __nv_bfloat16 hi[4], lo[4];
#pragma unroll
        for (int j = 0; j < 4; j++) split2(o[i][j] * inv, hi[j], lo[j]);
        size_t base = ((size_t)b * SS + q0 + r0 + i) * K3;
        uint4 pk;
        pk.x = pack2(hi[0], lo[0]);
        pk.y = pack2(hi[1], lo[1]);
        pk.z = pack2(hi[2], lo[2]);
        pk.w = pack2(hi[3], lo[3]);
        *(uint4*)&O[base + 2 * (h * HD + c0)] = pk;
        uint2 tl;
        tl.x = pack2(hi[0], hi[1]);
        tl.y = pack2(hi[2], hi[3]);
        *(uint2*)&O[base + 2048 + h * HD + c0] = tl;
    }
}

// ---------------------------------------------------------------------------
extern "C" void kernel_launch(void* const* d_in, const int* in_sizes, int n_in,
                              void* d_out, int out_size) {
    const float* x  = (const float*)d_in[0];
    const float* Wq = (const float*)d_in[1];
    const float* bq = (const float*)d_in[2];
    const float* Wk = (const float*)d_in[3];
    const float* bk = (const float*)d_in[4];
    const float* Wv = (const float*)d_in[5];
    const float* bv = (const float*)d_in[6];
    const float* Wo = (const float*)d_in[7];
    const float* bo = (const float*)d_in[8];

    __nv_bfloat16 *xTb, *wqb, *wkb, *wvb, *wob, *attb;
    float *q, *k, *v;
    cudaGetSymbolAddress((void**)&xTb, g_xTbig);
    cudaGetSymbolAddress((void**)&wqb, g_Wqb);
    cudaGetSymbolAddress((void**)&wkb, g_Wkb);
    cudaGetSymbolAddress((void**)&wvb, g_Wvb);
    cudaGetSymbolAddress((void**)&wob, g_Wob);
    cudaGetSymbolAddress((void**)&q, g_q);
    cudaGetSymbolAddress((void**)&k, g_k);
    cudaGetSymbolAddress((void**)&v, g_v);
    cudaGetSymbolAddress((void**)&attb, g_attbig);

    pe_transpose_split<<<dim3(SS / 32, DM / 32, BB), dim3(32, 32)>>>(x, xTb);
    wsplit_kernel<<<dim3(DM * DM / 256, 4), 256>>>(Wq, Wk, Wv, Wo, wqb, wkb, wvb, wob);

    cudaFuncSetAttribute(hmma_gemm, cudaFuncAttributeMaxDynamicSharedMemorySize, GEMM_SMEM);
    dim3 gg(DM / 128, (BB * SS) / 128);  // (8, 64)
    hmma_gemm<<<gg, 256, GEMM_SMEM>>>(xTb, wqb, bq, q, 0);
    hmma_gemm<<<gg, 256, GEMM_SMEM>>>(xTb, wkb, bk, k, 0);
    hmma_gemm<<<gg, 256, GEMM_SMEM>>>(xTb, wvb, bv, v, 0);

    int asmem = (3 * 64 * QPAD + 64 * 64) * (int)sizeof(float);
    cudaFuncSetAttribute(attn_kernel, cudaFuncAttributeMaxDynamicSharedMemorySize, asmem);
    attn_kernel<<<dim3(SS / 64, BB * HH), 256, asmem>>>(q, k, v, attb);

    hmma_gemm<<<gg, 256, GEMM_SMEM>>>(attb, wob, bo, (float*)d_out, 1);
}

// round 5
// speedup vs baseline: 2.2278x; 1.7366x over previous
#include <cuda_runtime.h>
#include <cuda_bf16.h>
#include <math.h>
#include <stdint.h>

#define BB 4
#define DM 1024
#define SS 2048
#define HH 16
#define HD 64
#define K3 3072   // tripled K for 1024-col GEMMs
#define AKK 192   // tripled K for 64-dim attention contractions

// ---------------- scratch (device globals; allocation-free) ----------------
__device__ __nv_bfloat16 g_xTbig[(size_t)BB * SS * K3];
__device__ __nv_bfloat16 g_Wqb[(size_t)DM * K3];
__device__ __nv_bfloat16 g_Wkb[(size_t)DM * K3];
__device__ __nv_bfloat16 g_Wvb[(size_t)DM * K3];
__device__ __nv_bfloat16 g_Wob[(size_t)DM * K3];
__device__ __nv_bfloat16 g_Qs[(size_t)BB * HH * SS * AKK];  // [(qh,ql)|qh], x0.125
__device__ __nv_bfloat16 g_Ks[(size_t)BB * HH * SS * AKK];  // [(kh,kh)|kl]
__device__ __nv_bfloat16 g_Vt[(size_t)BB * HH * (SS / 64) * HD * AKK]; // V^T per chunk
__device__ __nv_bfloat16 g_attbig[(size_t)BB * SS * K3];

// ---------------- helpers ----------------
__device__ __forceinline__ uint32_t smem_u32(const void* p) {
    uint32_t a;
    asm("{ .reg .u64 t; cvta.to.shared.u64 t, %1; cvt.u32.u64 %0, t; }" : "=r"(a) : "l"(p));
    return a;
}
__device__ __forceinline__ void cp16(uint32_t s, const void* g) {
    asm volatile("cp.async.cg.shared.global [%0], [%1], 16;" :: "r"(s), "l"(g) : "memory");
}
#define CP_COMMIT() asm volatile("cp.async.commit_group;" ::: "memory")
#define CP_WAIT1()  asm volatile("cp.async.wait_group 1;" ::: "memory")
#define CP_WAIT0()  asm volatile("cp.async.wait_group 0;" ::: "memory")

__device__ __forceinline__ void ldsm4(uint32_t* r, uint32_t addr) {
    asm volatile("ldmatrix.sync.aligned.m8n8.x4.shared.b16 {%0,%1,%2,%3}, [%4];"
                 : "=r"(r[0]), "=r"(r[1]), "=r"(r[2]), "=r"(r[3]) : "r"(addr));
}
__device__ __forceinline__ void mma16816(float* c, const uint32_t* a,
                                         uint32_t b0, uint32_t b1) {
    asm volatile("mma.sync.aligned.m16n8k16.row.col.f32.bf16.bf16.f32 "
                 "{%0,%1,%2,%3}, {%4,%5,%6,%7}, {%8,%9}, {%0,%1,%2,%3};"
                 : "+f"(c[0]), "+f"(c[1]), "+f"(c[2]), "+f"(c[3])
                 : "r"(a[0]), "r"(a[1]), "r"(a[2]), "r"(a[3]), "r"(b0), "r"(b1));
}
__device__ __forceinline__ void split2(float v, __nv_bfloat16& hi, __nv_bfloat16& lo) {
    hi = __float2bfloat16(v);
    lo = __float2bfloat16(v - __bfloat162float(hi));
}
__device__ __forceinline__ uint32_t pack2(__nv_bfloat16 a, __nv_bfloat16 b) {
    return (uint32_t)__bfloat16_as_ushort(a) | ((uint32_t)__bfloat16_as_ushort(b) << 16);
}

// ---------------------------------------------------------------------------
// Kernel 1: x[B,D,S] + PE -> xTbig rows [ (ah,al)x1024 | ah x1024 ]
// ---------------------------------------------------------------------------
__global__ void pe_transpose_split(const float* __restrict__ x,
                                   __nv_bfloat16* __restrict__ out) {
    __shared__ float tile[32][33];
    int b = blockIdx.z;
    int d0 = blockIdx.y * 32, s0 = blockIdx.x * 32;
    int d = d0 + threadIdx.y, s = s0 + threadIdx.x;
    float denom = expf((float)(d & ~1) * (-9.210340371976184f / (float)DM));
    float ang = (float)s * denom;
    float pe = (d & 1) ? cosf(ang) : sinf(ang);
    tile[threadIdx.y][threadIdx.x] = x[((size_t)b * DM + d) * SS + s] + pe;
    __syncthreads();
    int s2 = s0 + threadIdx.y, d2 = d0 + threadIdx.x;
    float v = tile[threadIdx.x][threadIdx.y];
    __nv_bfloat16 hi, lo; split2(v, hi, lo);
    size_t base = ((size_t)b * SS + s2) * K3;
    *(uint32_t*)&out[base + 2 * d2] = pack2(hi, lo);
    out[base + 2048 + d2] = hi;
}

// ---------------------------------------------------------------------------
// Kernel 1b: weight split -> rows [ (wh,wh)x1024 | wl x1024 ]
// ---------------------------------------------------------------------------
__global__ void wsplit_kernel(const float* __restrict__ w0, const float* __restrict__ w1,
                              const float* __restrict__ w2, const float* __restrict__ w3,
                              __nv_bfloat16* o0, __nv_bfloat16* o1,
                              __nv_bfloat16* o2, __nv_bfloat16* o3) {
    const float* src; __nv_bfloat16* dst;
    switch (blockIdx.y) {
        case 0: src = w0; dst = o0; break;
        case 1: src = w1; dst = o1; break;
        case 2: src = w2; dst = o2; break;
        default: src = w3; dst = o3; break;
    }
    int idx = blockIdx.x * 256 + threadIdx.x;
    int n = idx >> 10, dcol = idx & 1023;
    __nv_bfloat16 hi, lo; split2(src[idx], hi, lo);
    size_t base = (size_t)n * K3;
    *(uint32_t*)&dst[base + 2 * dcol] = pack2(hi, hi);
    dst[base + 2048 + dcol] = lo;
}

// ---------------------------------------------------------------------------
// Kernel 2: HMMA GEMM C[8192,1024] = A[8192,K3]·W[1024,K3]^T + bias
// modes: 0 -> Q split layout, 1 -> K split layout, 2 -> V^T split layout,
//        3 -> fp32 [B,D,S] final output
// ---------------------------------------------------------------------------
#define STG 20480
#define GEMM_SMEM (128 * 129 * 4)

__global__ __launch_bounds__(256, 2)
void hmma_gemm(const __nv_bfloat16* __restrict__ A, const __nv_bfloat16* __restrict__ W,
               const float* __restrict__ bias, void* __restrict__ outv, int mode) {
    extern __shared__ char smem[];
    const uint32_t sb = smem_u32(smem);
    const int tid = threadIdx.x, wid = tid >> 5, lane = tid & 31;
    const int wr = wid >> 1, wc = wid & 1;
    const int mBase = blockIdx.y * 128, nBase = blockIdx.x * 128;

    float acc[2][8][4];
#pragma unroll
    for (int i = 0; i < 2; i++)
#pragma unroll
        for (int j = 0; j < 8; j++)
#pragma unroll
            for (int r = 0; r < 4; r++) acc[i][j][r] = 0.f;

    const int r0 = tid >> 2, c4 = tid & 3;
    const __nv_bfloat16* gA = A + (size_t)(mBase + r0) * K3 + c4 * 8;
    const __nv_bfloat16* gW = W + (size_t)(nBase + r0) * K3 + c4 * 8;

#define LOAD_CHUNK(c, st)                                                     \
    do {                                                                      \
        uint32_t sA = sb + (st) * STG + r0 * 80 + c4 * 16;                    \
        uint32_t sW = sA + 10240;                                             \
        cp16(sA, gA + (c) * 32);                                              \
        cp16(sA + 64 * 80, gA + (size_t)64 * K3 + (c) * 32);                  \
        cp16(sW, gW + (c) * 32);                                              \
        cp16(sW + 64 * 80, gW + (size_t)64 * K3 + (c) * 32);                  \
        CP_COMMIT();                                                          \
    } while (0)

    LOAD_CHUNK(0, 0);
    LOAD_CHUNK(1, 1);

    const uint32_t aB = (wr * 32 + (lane & 15)) * 80 + (lane >> 4) * 16;
    const uint32_t bB = 10240 + (wc * 64 + (lane & 15)) * 80 + (lane >> 4) * 16;

    const int NCH = K3 / 32;  // 96
    for (int c = 0; c < NCH; c++) {
        if (c == NCH - 1) CP_WAIT0(); else CP_WAIT1();
        __syncthreads();
        const uint32_t stg = sb + (c & 1) * STG;
#pragma unroll
        for (int ks = 0; ks < 2; ks++) {
            uint32_t a[2][4], b[4][4];
            ldsm4(a[0], stg + aB + ks * 32);
            ldsm4(a[1], stg + aB + 16 * 80 + ks * 32);
#pragma unroll
            for (int j2 = 0; j2 < 4; j2++)
                ldsm4(b[j2], stg + bB + j2 * 16 * 80 + ks * 32);
#pragma unroll
            for (int mi = 0; mi < 2; mi++)
#pragma unroll
                for (int nj = 0; nj < 8; nj++)
                    mma16816(acc[mi][nj], a[mi],
                             b[nj >> 1][nj & 1], b[nj >> 1][(nj & 1) + 2]);
        }
        __syncthreads();
        if (c + 2 < NCH) LOAD_CHUNK(c + 2, c & 1);
    }
#undef LOAD_CHUNK

    __syncthreads();
    float* ep = (float*)smem;
#pragma unroll
    for (int mi = 0; mi < 2; mi++)
#pragma unroll
        for (int nj = 0; nj < 8; nj++) {
            int row = wr * 32 + mi * 16 + (lane >> 2);
            int col = wc * 64 + nj * 8 + (lane & 3) * 2;
            ep[row * 129 + col] = acc[mi][nj][0];
            ep[row * 129 + col + 1] = acc[mi][nj][1];
            ep[(row + 8) * 129 + col] = acc[mi][nj][2];
            ep[(row + 8) * 129 + col + 1] = acc[mi][nj][3];
        }
    __syncthreads();

    if (mode == 3) {  // final [B,D,S] fp32
        float* out = (float*)outv;
        int nl = tid >> 1;
        int n = nBase + nl;
        float bn = bias[n];
#pragma unroll
        for (int ii = 0; ii < 16; ii++) {
            int sl = (tid & 1) * 64 + ii * 4;
            int m0 = mBase + sl, b = m0 >> 11, s = m0 & 2047;
            float4 v;
            v.x = ep[(sl + 0) * 129 + nl] + bn;
            v.y = ep[(sl + 1) * 129 + nl] + bn;
            v.z = ep[(sl + 2) * 129 + nl] + bn;
            v.w = ep[(sl + 3) * 129 + nl] + bn;
            *(float4*)&out[((size_t)b * DM + n) * SS + s] = v;
        }
    } else if (mode == 2) {  // V^T split: [bh, chunk, d, 192]
        __nv_bfloat16* out = (__nv_bfloat16*)outv;
        int nl = tid >> 1, ch = tid & 1;
        int b = mBase >> 11, s0 = mBase & 2047;
        int h = (nBase + nl) >> 6, dd = (nBase + nl) & 63;
        float bn = bias[nBase + nl];
        size_t vb = (((size_t)(b * HH + h)) * 32 + (s0 >> 6) + ch) * (64 * AKK)
                    + (size_t)dd * AKK;
#pragma unroll
        for (int j = 0; j < 64; j += 2) {
            float v0 = ep[(ch * 64 + j) * 129 + nl] + bn;
            float v1 = ep[(ch * 64 + j + 1) * 129 + nl] + bn;
            __nv_bfloat16 h0, l0, h1, l1;
            split2(v0, h0, l0); split2(v1, h1, l1);
            uint2 pp; pp.x = pack2(h0, h0); pp.y = pack2(h1, h1);
            *(uint2*)&out[vb + 2 * j] = pp;
            *(uint32_t*)&out[vb + 128 + j] = pack2(l0, l1);
        }
    } else {  // mode 0 (Q) / mode 1 (K): split rows over hd
        __nv_bfloat16* out = (__nv_bfloat16*)outv;
#pragma unroll
        for (int i = 0; i < 8; i++) {
            int r = (tid >> 4) + i * 16;
            int cc = (tid & 15) * 8;
            int m = mBase + r, b = m >> 11, s = m & 2047;
            int n = nBase + cc, h = n >> 6, dd = n & 63;
            size_t base = ((size_t)(b * HH + h) * SS + s) * AKK;
            uint32_t pr[8];
            __nv_bfloat16 tl[8];
#pragma unroll
            for (int j = 0; j < 8; j++) {
                float v = ep[r * 129 + cc + j] + bias[n + j];
                if (mode == 0) v *= 0.125f;
                __nv_bfloat16 hi, lo; split2(v, hi, lo);
                if (mode == 0) { pr[j] = pack2(hi, lo); tl[j] = hi; }
                else           { pr[j] = pack2(hi, hi); tl[j] = lo; }
            }
            *(uint4*)&out[base + 2 * dd] = *(uint4*)&pr[0];
            *(uint4*)&out[base + 2 * dd + 8] = *(uint4*)&pr[4];
            *(uint4*)&out[base + 128 + dd] = *(uint4*)&tl[0];
        }
    }
}

// ---------------------------------------------------------------------------
// Kernel 3: HMMA flash attention. CTA = (b,h) x 128 q-rows. 8 warps,
// warp = 16 q-rows x 64 keys (softmax warp-local). 2-stage cp.async K/V.
// All contractions K=192 split-bf16. Emits split layout for Wo GEMM.
// ---------------------------------------------------------------------------
#define APITCH 400
#define AQO 0
#define AKO 51200
#define AVO 102400
#define APO 153600
#define ASTG 25600
#define ATTN_SMEM 204800

__device__ __forceinline__ void load_kv(uint32_t sb, int tid,
                                        const __nv_bfloat16* Kg,
                                        const __nv_bfloat16* Vg, int kt, int st) {
#pragma unroll
    for (int i = 0; i < 6; i++) {
        int idx = tid + i * 256;
        int row = idx / 24, seg = idx - row * 24;
        uint32_t so = st * ASTG + row * APITCH + seg * 16;
        size_t go = ((size_t)kt * 64 + row) * AKK + seg * 8;
        cp16(sb + AKO + so, Kg + go);
        cp16(sb + AVO + so, Vg + go);
    }
    CP_COMMIT();
}

__global__ __launch_bounds__(256, 1)
void attn_hmma(const __nv_bfloat16* __restrict__ Qs,
               const __nv_bfloat16* __restrict__ Ks,
               const __nv_bfloat16* __restrict__ Vt,
               __nv_bfloat16* __restrict__ O) {
    extern __shared__ char smem[];
    const uint32_t sb = smem_u32(smem);
    const int tid = threadIdx.x, w = tid >> 5, lane = tid & 31;
    const int bh = blockIdx.y;
    const int q0 = blockIdx.x * 128;
    const __nv_bfloat16* Qg = Qs + ((size_t)bh * SS + q0) * AKK;
    const __nv_bfloat16* Kg = Ks + (size_t)bh * SS * AKK;
    const __nv_bfloat16* Vg = Vt + (size_t)bh * (32 * 64 * AKK);

    // Q tile: 128 rows x 384B
#pragma unroll
    for (int i = 0; i < 12; i++) {
        int idx = tid + i * 256;
        int row = idx / 24, seg = idx - row * 24;
        cp16(sb + AQO + row * APITCH + seg * 16, Qg + (size_t)row * AKK + seg * 8);
    }
    load_kv(sb, tid, Kg, Vg, 0, 0);  // group0 = Q + KV0
    load_kv(sb, tid, Kg, Vg, 1, 1);  // group1 = KV1

    float o[8][4];
    float mi[2] = {-1e30f, -1e30f}, li[2] = {0.f, 0.f};
#pragma unroll
    for (int nj = 0; nj < 8; nj++)
#pragma unroll
        for (int r = 0; r < 4; r++) o[nj][r] = 0.f;

    const int q4 = lane & 3;
    const int r1 = w * 16 + (lane >> 2);
    const uint32_t aQ = sb + AQO + (w * 16 + (lane & 15)) * APITCH + (lane >> 4) * 16;
    const uint32_t aP = sb + APO + (w * 16 + (lane & 15)) * APITCH + (lane >> 4) * 16;
    const uint32_t bK = sb + AKO + (lane & 15) * APITCH + (lane >> 4) * 16;
    const uint32_t bV = sb + AVO + (lane & 15) * APITCH + (lane >> 4) * 16;

    for (int kt = 0; kt < 32; kt++) {
        if (kt == 31) CP_WAIT0(); else CP_WAIT1();
        __syncthreads();
        const uint32_t stoff = (kt & 1) * ASTG;

        // --- S = Q K^T ---
        float sc[8][4];
#pragma unroll
        for (int nj = 0; nj < 8; nj++)
#pragma unroll
            for (int r = 0; r < 4; r++) sc[nj][r] = 0.f;
#pragma unroll
        for (int ks = 0; ks < 12; ks++) {
            uint32_t a[4], b[4][4];
            ldsm4(a, aQ + ks * 32);
#pragma unroll
            for (int j2 = 0; j2 < 4; j2++)
                ldsm4(b[j2], bK + stoff + j2 * 16 * APITCH + ks * 32);
#pragma unroll
            for (int nj = 0; nj < 8; nj++)
                mma16816(sc[nj], a, b[nj >> 1][nj & 1], b[nj >> 1][(nj & 1) + 2]);
        }

        // --- online softmax (warp-local rows), write split P ---
#pragma unroll
        for (int rr = 0; rr < 2; rr++) {
            float mx = -1e30f;
#pragma unroll
            for (int nj = 0; nj < 8; nj++)
                mx = fmaxf(mx, fmaxf(sc[nj][rr * 2], sc[nj][rr * 2 + 1]));
            mx = fmaxf(mx, __shfl_xor_sync(0xffffffffu, mx, 1));
            mx = fmaxf(mx, __shfl_xor_sync(0xffffffffu, mx, 2));
            float mn = fmaxf(mi[rr], mx);
            float rs = 0.f;
            uint32_t prow = sb + APO + (r1 + rr * 8) * APITCH;
#pragma unroll
            for (int nj = 0; nj < 8; nj++) {
                float p0 = __expf(sc[nj][rr * 2] - mn);
                float p1 = __expf(sc[nj][rr * 2 + 1] - mn);
                rs += p0 + p1;
                __nv_bfloat16 h0, l0, h1, l1;
                split2(p0, h0, l0); split2(p1, h1, l1);
                int k0 = nj * 8 + 2 * q4;
                asm volatile("st.shared.v2.b32 [%0], {%1,%2};"
                             :: "r"(prow + 4 * k0), "r"(pack2(h0, l0)), "r"(pack2(h1, l1))
                             : "memory");
                asm volatile("st.shared.b32 [%0], %1;"
                             :: "r"(prow + 256 + 2 * k0), "r"(pack2(h0, h1)) : "memory");
            }
            rs += __shfl_xor_sync(0xffffffffu, rs, 1);
            rs += __shfl_xor_sync(0xffffffffu, rs, 2);
            float f = __expf(mi[rr] - mn);
            li[rr] = li[rr] * f + rs;
            mi[rr] = mn;
#pragma unroll
            for (int nj = 0; nj < 8; nj++) {
                o[nj][rr * 2] *= f;
                o[nj][rr * 2 + 1] *= f;
            }
        }
        __syncwarp();  // P rows are warp-private; order STS -> ldmatrix

        // --- O += P V ---
#pragma unroll
        for (int ks = 0; ks < 12; ks++) {
            uint32_t a[4], b[4][4];
            ldsm4(a, aP + ks * 32);
#pragma unroll
            for (int j2 = 0; j2 < 4; j2++)
                ldsm4(b[j2], bV + stoff + j2 * 16 * APITCH + ks * 32);
#pragma unroll
            for (int nj = 0; nj < 8; nj++)
                mma16816(o[nj], a, b[nj >> 1][nj & 1], b[nj >> 1][(nj & 1) + 2]);
        }
        __syncthreads();  // all warps done with K/V(kt) buffer
        if (kt + 2 < 32) load_kv(sb, tid, Kg, Vg, kt + 2, kt & 1);
    }

    // --- epilogue: normalize, emit split layout for Wo GEMM ---
    const int b_ = bh >> 4, h_ = bh & 15;
#pragma unroll
    for (int rr = 0; rr < 2; rr++) {
        float inv = 1.f / li[rr];
        size_t base = ((size_t)b_ * SS + q0 + r1 + rr * 8) * (size_t)K3;
#pragma unroll
        for (int nj = 0; nj < 8; nj++) {
            int d = nj * 8 + 2 * q4;
            float v0 = o[nj][rr * 2] * inv, v1 = o[nj][rr * 2 + 1] * inv;
            __nv_bfloat16 h0, l0, h1, l1;
            split2(v0, h0, l0); split2(v1, h1, l1);
            uint2 pp; pp.x = pack2(h0, l0); pp.y = pack2(h1, l1);
            *(uint2*)&O[base + 2 * (h_ * 64 + d)] = pp;
            *(uint32_t*)&O[base + 2048 + h_ * 64 + d] = pack2(h0, h1);
        }
    }
}

// ---------------------------------------------------------------------------
extern "C" void kernel_launch(void* const* d_in, const int* in_sizes, int n_in,
                              void* d_out, int out_size) {
    const float* x  = (const float*)d_in[0];
    const float* Wq = (const float*)d_in[1];
    const float* bq = (const float*)d_in[2];
    const float* Wk = (const float*)d_in[3];
    const float* bk = (const float*)d_in[4];
    const float* Wv = (const float*)d_in[5];
    const float* bv = (const float*)d_in[6];
    const float* Wo = (const float*)d_in[7];
    const float* bo = (const float*)d_in[8];

    __nv_bfloat16 *xTb, *wqb, *wkb, *wvb, *wob, *qs, *ks, *vt, *attb;
    cudaGetSymbolAddress((void**)&xTb, g_xTbig);
    cudaGetSymbolAddress((void**)&wqb, g_Wqb);
    cudaGetSymbolAddress((void**)&wkb, g_Wkb);
    cudaGetSymbolAddress((void**)&wvb, g_Wvb);
    cudaGetSymbolAddress((void**)&wob, g_Wob);
    cudaGetSymbolAddress((void**)&qs, g_Qs);
    cudaGetSymbolAddress((void**)&ks, g_Ks);
    cudaGetSymbolAddress((void**)&vt, g_Vt);
    cudaGetSymbolAddress((void**)&attb, g_attbig);

    pe_transpose_split<<<dim3(SS / 32, DM / 32, BB), dim3(32, 32)>>>(x, xTb);
    wsplit_kernel<<<dim3(DM * DM / 256, 4), 256>>>(Wq, Wk, Wv, Wo, wqb, wkb, wvb, wob);

    cudaFuncSetAttribute(hmma_gemm, cudaFuncAttributeMaxDynamicSharedMemorySize, GEMM_SMEM);
    dim3 gg(DM / 128, (BB * SS) / 128);  // (8, 64)
    hmma_gemm<<<gg, 256, GEMM_SMEM>>>(xTb, wqb, bq, qs, 0);
    hmma_gemm<<<gg, 256, GEMM_SMEM>>>(xTb, wkb, bk, ks, 1);
    hmma_gemm<<<gg, 256, GEMM_SMEM>>>(xTb, wvb, bv, vt, 2);

    cudaFuncSetAttribute(attn_hmma, cudaFuncAttributeMaxDynamicSharedMemorySize, ATTN_SMEM);
    attn_hmma<<<dim3(SS / 128, BB * HH), 256, ATTN_SMEM>>>(qs, ks, vt, attb);

    hmma_gemm<<<gg, 256, GEMM_SMEM>>>(attb, wob, bo, d_out, 3);
}

// round 6
// speedup vs baseline: 2.3638x; 1.0611x over previous
#include <cuda_runtime.h>
#include <cuda_bf16.h>
#include <math.h>
#include <stdint.h>

#define BB 4
#define DM 1024
#define SS 2048
#define HH 16
#define HD 64
#define K3 3072   // tripled K for 1024-col GEMMs
#define AKK 192   // tripled K for 64-dim attention contractions

// ---------------- scratch (device globals; allocation-free) ----------------
__device__ __nv_bfloat16 g_xTbig[(size_t)BB * SS * K3];
__device__ __nv_bfloat16 g_Wqb[(size_t)DM * K3];
__device__ __nv_bfloat16 g_Wkb[(size_t)DM * K3];
__device__ __nv_bfloat16 g_Wvb[(size_t)DM * K3];
__device__ __nv_bfloat16 g_Wob[(size_t)DM * K3];
__device__ __nv_bfloat16 g_Qs[(size_t)BB * HH * SS * AKK];  // [(qh,ql)|qh], x0.125
__device__ __nv_bfloat16 g_Ks[(size_t)BB * HH * SS * AKK];  // [(kh,kh)|kl]
__device__ __nv_bfloat16 g_Vt[(size_t)BB * HH * (SS / 64) * HD * AKK]; // V^T [vh|vh|vl]
__device__ __nv_bfloat16 g_attbig[(size_t)BB * SS * K3];

// ---------------- helpers ----------------
__device__ __forceinline__ uint32_t smem_u32(const void* p) {
    uint32_t a;
    asm("{ .reg .u64 t; cvta.to.shared.u64 t, %1; cvt.u32.u64 %0, t; }" : "=r"(a) : "l"(p));
    return a;
}
__device__ __forceinline__ void cp16(uint32_t s, const void* g) {
    asm volatile("cp.async.cg.shared.global [%0], [%1], 16;" :: "r"(s), "l"(g) : "memory");
}
#define CP_COMMIT() asm volatile("cp.async.commit_group;" ::: "memory")
#define CP_WAIT2()  asm volatile("cp.async.wait_group 2;" ::: "memory")
#define CP_WAIT1()  asm volatile("cp.async.wait_group 1;" ::: "memory")
#define CP_WAIT0()  asm volatile("cp.async.wait_group 0;" ::: "memory")

__device__ __forceinline__ void ldsm4(uint32_t* r, uint32_t addr) {
    asm volatile("ldmatrix.sync.aligned.m8n8.x4.shared.b16 {%0,%1,%2,%3}, [%4];"
                 : "=r"(r[0]), "=r"(r[1]), "=r"(r[2]), "=r"(r[3]) : "r"(addr));
}
__device__ __forceinline__ void mma16816(float* c, const uint32_t* a,
                                         uint32_t b0, uint32_t b1) {
    asm volatile("mma.sync.aligned.m16n8k16.row.col.f32.bf16.bf16.f32 "
                 "{%0,%1,%2,%3}, {%4,%5,%6,%7}, {%8,%9}, {%0,%1,%2,%3};"
                 : "+f"(c[0]), "+f"(c[1]), "+f"(c[2]), "+f"(c[3])
                 : "r"(a[0]), "r"(a[1]), "r"(a[2]), "r"(a[3]), "r"(b0), "r"(b1));
}
__device__ __forceinline__ void split2(float v, __nv_bfloat16& hi, __nv_bfloat16& lo) {
    hi = __float2bfloat16(v);
    lo = __float2bfloat16(v - __bfloat162float(hi));
}
__device__ __forceinline__ uint32_t pack2(__nv_bfloat16 a, __nv_bfloat16 b) {
    return (uint32_t)__bfloat16_as_ushort(a) | ((uint32_t)__bfloat16_as_ushort(b) << 16);
}

// ---------------------------------------------------------------------------
// Kernel 1: x[B,D,S] + PE -> xTbig rows [ (ah,al)x1024 | ah x1024 ]
// ---------------------------------------------------------------------------
__global__ void pe_transpose_split(const float* __restrict__ x,
                                   __nv_bfloat16* __restrict__ out) {
    __shared__ float tile[32][33];
    int b = blockIdx.z;
    int d0 = blockIdx.y * 32, s0 = blockIdx.x * 32;
    int d = d0 + threadIdx.y, s = s0 + threadIdx.x;
    float denom = expf((float)(d & ~1) * (-9.210340371976184f / (float)DM));
    float ang = (float)s * denom;
    float pe = (d & 1) ? cosf(ang) : sinf(ang);
    tile[threadIdx.y][threadIdx.x] = x[((size_t)b * DM + d) * SS + s] + pe;
    __syncthreads();
    int s2 = s0 + threadIdx.y, d2 = d0 + threadIdx.x;
    float v = tile[threadIdx.x][threadIdx.y];
    __nv_bfloat16 hi, lo; split2(v, hi, lo);
    size_t base = ((size_t)b * SS + s2) * K3;
    *(uint32_t*)&out[base + 2 * d2] = pack2(hi, lo);
    out[base + 2048 + d2] = hi;
}

// ---------------------------------------------------------------------------
// Kernel 1b: weight split -> rows [ (wh,wh)x1024 | wl x1024 ]
// ---------------------------------------------------------------------------
__global__ void wsplit_kernel(const float* __restrict__ w0, const float* __restrict__ w1,
                              const float* __restrict__ w2, const float* __restrict__ w3,
                              __nv_bfloat16* o0, __nv_bfloat16* o1,
                              __nv_bfloat16* o2, __nv_bfloat16* o3) {
    const float* src; __nv_bfloat16* dst;
    switch (blockIdx.y) {
        case 0: src = w0; dst = o0; break;
        case 1: src = w1; dst = o1; break;
        case 2: src = w2; dst = o2; break;
        default: src = w3; dst = o3; break;
    }
    int idx = blockIdx.x * 256 + threadIdx.x;
    int n = idx >> 10, dcol = idx & 1023;
    __nv_bfloat16 hi, lo; split2(src[idx], hi, lo);
    size_t base = (size_t)n * K3;
    *(uint32_t*)&dst[base + 2 * dcol] = pack2(hi, hi);
    dst[base + 2048 + dcol] = lo;
}

// ---------------------------------------------------------------------------
// Kernel 2: HMMA GEMM C[8192,1024] = A[8192,K3]·W[1024,K3]^T + bias
// 4-stage cp.async ring, ONE __syncthreads per K-chunk.
// modes: 0 Q-split, 1 K-split, 2 V^T-split [vh|vh|vl], 3 fp32 [B,D,S]
// ---------------------------------------------------------------------------
#define STG 20480
#define GEMM_SMEM 81920  // 4 stages x 20480; epilogue (66048 B) overlays

__global__ __launch_bounds__(256, 2)
void hmma_gemm(const __nv_bfloat16* __restrict__ A, const __nv_bfloat16* __restrict__ W,
               const float* __restrict__ bias, void* __restrict__ outv, int mode) {
    extern __shared__ char smem[];
    const uint32_t sb = smem_u32(smem);
    const int tid = threadIdx.x, wid = tid >> 5, lane = tid & 31;
    const int wr = wid >> 1, wc = wid & 1;
    const int mBase = blockIdx.y * 128, nBase = blockIdx.x * 128;

    float acc[2][8][4];
#pragma unroll
    for (int i = 0; i < 2; i++)
#pragma unroll
        for (int j = 0; j < 8; j++)
#pragma unroll
            for (int r = 0; r < 4; r++) acc[i][j][r] = 0.f;

    const int r0 = tid >> 2, c4 = tid & 3;
    const __nv_bfloat16* gA = A + (size_t)(mBase + r0) * K3 + c4 * 8;
    const __nv_bfloat16* gW = W + (size_t)(nBase + r0) * K3 + c4 * 8;

#define LOAD_CHUNK(c, st)                                                     \
    do {                                                                      \
        uint32_t sA = sb + (st) * STG + r0 * 80 + c4 * 16;                    \
        uint32_t sW = sA + 10240;                                             \
        cp16(sA, gA + (c) * 32);                                              \
        cp16(sA + 64 * 80, gA + (size_t)64 * K3 + (c) * 32);                  \
        cp16(sW, gW + (c) * 32);                                              \
        cp16(sW + 64 * 80, gW + (size_t)64 * K3 + (c) * 32);                  \
        CP_COMMIT();                                                          \
    } while (0)

    LOAD_CHUNK(0, 0);
    LOAD_CHUNK(1, 1);
    LOAD_CHUNK(2, 2);

    const uint32_t aB = (wr * 32 + (lane & 15)) * 80 + (lane >> 4) * 16;
    const uint32_t bB = 10240 + (wc * 64 + (lane & 15)) * 80 + (lane >> 4) * 16;

    const int NCH = K3 / 32;  // 96
    for (int c = 0; c < NCH; c++) {
        if (c <= NCH - 3) CP_WAIT2();
        else if (c == NCH - 2) CP_WAIT1();
        else CP_WAIT0();
        __syncthreads();  // data ready + prior-stage reads fenced
        if (c + 3 < NCH) LOAD_CHUNK(c + 3, (c + 3) & 3);
        const uint32_t stg = sb + (c & 3) * STG;
#pragma unroll
        for (int ks = 0; ks < 2; ks++) {
            uint32_t a[2][4], b[4][4];
            ldsm4(a[0], stg + aB + ks * 32);
            ldsm4(a[1], stg + aB + 16 * 80 + ks * 32);
#pragma unroll
            for (int j2 = 0; j2 < 4; j2++)
                ldsm4(b[j2], stg + bB + j2 * 16 * 80 + ks * 32);
#pragma unroll
            for (int mi = 0; mi < 2; mi++)
#pragma unroll
                for (int nj = 0; nj < 8; nj++)
                    mma16816(acc[mi][nj], a[mi],
                             b[nj >> 1][nj & 1], b[nj >> 1][(nj & 1) + 2]);
        }
    }
#undef LOAD_CHUNK

    __syncthreads();
    float* ep = (float*)smem;
#pragma unroll
    for (int mi = 0; mi < 2; mi++)
#pragma unroll
        for (int nj = 0; nj < 8; nj++) {
            int row = wr * 32 + mi * 16 + (lane >> 2);
            int col = wc * 64 + nj * 8 + (lane & 3) * 2;
            ep[row * 129 + col] = acc[mi][nj][0];
            ep[row * 129 + col + 1] = acc[mi][nj][1];
            ep[(row + 8) * 129 + col] = acc[mi][nj][2];
            ep[(row + 8) * 129 + col + 1] = acc[mi][nj][3];
        }
    __syncthreads();

    if (mode == 3) {  // final [B,D,S] fp32
        float* out = (float*)outv;
        int nl = tid >> 1;
        int n = nBase + nl;
        float bn = bias[n];
#pragma unroll
        for (int ii = 0; ii < 16; ii++) {
            int sl = (tid & 1) * 64 + ii * 4;
            int m0 = mBase + sl, b = m0 >> 11, s = m0 & 2047;
            float4 v;
            v.x = ep[(sl + 0) * 129 + nl] + bn;
            v.y = ep[(sl + 1) * 129 + nl] + bn;
            v.z = ep[(sl + 2) * 129 + nl] + bn;
            v.w = ep[(sl + 3) * 129 + nl] + bn;
            *(float4*)&out[((size_t)b * DM + n) * SS + s] = v;
        }
    } else if (mode == 2) {  // V^T plain blocks: [bh, chunk, d, [vh|vh|vl]]
        __nv_bfloat16* out = (__nv_bfloat16*)outv;
        int nl = tid >> 1, ch = tid & 1;
        int b = mBase >> 11, s0 = mBase & 2047;
        int h = (nBase + nl) >> 6, dd = (nBase + nl) & 63;
        float bn = bias[nBase + nl];
        size_t vb = (((size_t)(b * HH + h)) * 32 + (s0 >> 6) + ch) * (64 * AKK)
                    + (size_t)dd * AKK;
#pragma unroll
        for (int j = 0; j < 64; j += 2) {
            float v0 = ep[(ch * 64 + j) * 129 + nl] + bn;
            float v1 = ep[(ch * 64 + j + 1) * 129 + nl] + bn;
            __nv_bfloat16 h0, l0, h1, l1;
            split2(v0, h0, l0); split2(v1, h1, l1);
            uint32_t hp = pack2(h0, h1);
            *(uint32_t*)&out[vb + j] = hp;
            *(uint32_t*)&out[vb + 64 + j] = hp;
            *(uint32_t*)&out[vb + 128 + j] = pack2(l0, l1);
        }
    } else {  // mode 0 (Q) / mode 1 (K)
        __nv_bfloat16* out = (__nv_bfloat16*)outv;
#pragma unroll
        for (int i = 0; i < 8; i++) {
            int r = (tid >> 4) + i * 16;
            int cc = (tid & 15) * 8;
            int m = mBase + r, b = m >> 11, s = m & 2047;
            int n = nBase + cc, h = n >> 6, dd = n & 63;
            size_t base = ((size_t)(b * HH + h) * SS + s) * AKK;
            uint32_t pr[8];
            __nv_bfloat16 tl[8];
#pragma unroll
            for (int j = 0; j < 8; j++) {
                float v = ep[r * 129 + cc + j] + bias[n + j];
                if (mode == 0) v *= 0.125f;
                __nv_bfloat16 hi, lo; split2(v, hi, lo);
                if (mode == 0) { pr[j] = pack2(hi, lo); tl[j] = hi; }
                else           { pr[j] = pack2(hi, hi); tl[j] = lo; }
            }
            *(uint4*)&out[base + 2 * dd] = *(uint4*)&pr[0];
            *(uint4*)&out[base + 2 * dd + 8] = *(uint4*)&pr[4];
            *(uint4*)&out[base + 128 + dd] = *(uint4*)&tl[0];
        }
    }
}

// ---------------------------------------------------------------------------
// Kernel 3: HMMA flash attention, register-resident P.
// CTA = (b,h) x 128 q-rows; 8 warps x (16q x 64k). 3-stage cp.async KV ring,
// one __syncthreads per tile. PV contraction order [P_hi | P_lo | P_hi]
// against V^T [vh | vh | vl] -> C-fragments convert to A-fragments in regs.
// ---------------------------------------------------------------------------
#define APITCH 400
#define AKO 51200      // Q occupies [0, 51200)
#define ASTG 51200     // one KV stage: K 25600 + V 25600
#define ATTN_SMEM 204800

__device__ __forceinline__ void load_kv(uint32_t sb, int tid,
                                        const __nv_bfloat16* Kg,
                                        const __nv_bfloat16* Vg, int kt, int st) {
#pragma unroll
    for (int i = 0; i < 6; i++) {
        int idx = tid + i * 256;
        int row = idx / 24, seg = idx - row * 24;
        uint32_t so = AKO + st * ASTG + row * APITCH + seg * 16;
        size_t go = ((size_t)kt * 64 + row) * AKK + seg * 8;
        cp16(so + sb, Kg + go);
        cp16(so + sb + 25600, Vg + go);
    }
    CP_COMMIT();
}

__global__ __launch_bounds__(256, 1)
void attn_hmma(const __nv_bfloat16* __restrict__ Qs,
               const __nv_bfloat16* __restrict__ Ks,
               const __nv_bfloat16* __restrict__ Vt,
               __nv_bfloat16* __restrict__ O) {
    extern __shared__ char smem[];
    const uint32_t sb = smem_u32(smem);
    const int tid = threadIdx.x, w = tid >> 5, lane = tid & 31;
    const int bh = blockIdx.y;
    const int q0 = blockIdx.x * 128;
    const __nv_bfloat16* Qg = Qs + ((size_t)bh * SS + q0) * AKK;
    const __nv_bfloat16* Kg = Ks + (size_t)bh * SS * AKK;
    const __nv_bfloat16* Vg = Vt + (size_t)bh * (32 * 64 * AKK);

    // prologue: Q (joins group 0 with KV0), then KV1
#pragma unroll
    for (int i = 0; i < 12; i++) {
        int idx = tid + i * 256;
        int row = idx / 24, seg = idx - row * 24;
        cp16(sb + row * APITCH + seg * 16, Qg + (size_t)row * AKK + seg * 8);
    }
    load_kv(sb, tid, Kg, Vg, 0, 0);
    load_kv(sb, tid, Kg, Vg, 1, 1);

    float o[8][4];
    float mi[2] = {-1e30f, -1e30f}, li[2] = {0.f, 0.f};
#pragma unroll
    for (int nj = 0; nj < 8; nj++)
#pragma unroll
        for (int r = 0; r < 4; r++) o[nj][r] = 0.f;

    const int q4 = lane & 3;
    const int r1 = w * 16 + (lane >> 2);
    const uint32_t aQ = sb + (w * 16 + (lane & 15)) * APITCH + (lane >> 4) * 16;
    const uint32_t bKb = sb + AKO + (lane & 15) * APITCH + (lane >> 4) * 16;

    for (int kt = 0; kt < 32; kt++) {
        if (kt == 31) CP_WAIT0(); else CP_WAIT1();
        __syncthreads();
        if (kt + 2 < 32) load_kv(sb, tid, Kg, Vg, kt + 2, (kt + 2) % 3);
        const uint32_t stoff = (kt % 3) * ASTG;

        // --- S = Q K^T ---
        float sc[8][4];
#pragma unroll
        for (int nj = 0; nj < 8; nj++)
#pragma unroll
            for (int r = 0; r < 4; r++) sc[nj][r] = 0.f;
#pragma unroll
        for (int ks = 0; ks < 12; ks++) {
            uint32_t a[4], b[4][4];
            ldsm4(a, aQ + ks * 32);
#pragma unroll
            for (int j2 = 0; j2 < 4; j2++)
                ldsm4(b[j2], bKb + stoff + j2 * 16 * APITCH + ks * 32);
#pragma unroll
            for (int nj = 0; nj < 8; nj++)
                mma16816(sc[nj], a, b[nj >> 1][nj & 1], b[nj >> 1][(nj & 1) + 2]);
        }

        // --- online softmax; P -> register A-fragments (hi & lo) ---
        uint32_t aPhi[4][4], aPlo[4][4];
#pragma unroll
        for (int rr = 0; rr < 2; rr++) {
            float mx = -1e30f;
#pragma unroll
            for (int nj = 0; nj < 8; nj++)
                mx = fmaxf(mx, fmaxf(sc[nj][rr * 2], sc[nj][rr * 2 + 1]));
            mx = fmaxf(mx, __shfl_xor_sync(0xffffffffu, mx, 1));
            mx = fmaxf(mx, __shfl_xor_sync(0xffffffffu, mx, 2));
            float mn = fmaxf(mi[rr], mx);
            float rs = 0.f;
#pragma unroll
            for (int nj = 0; nj < 8; nj++) {
                float p0 = __expf(sc[nj][rr * 2] - mn);
                float p1 = __expf(sc[nj][rr * 2 + 1] - mn);
                rs += p0 + p1;
                __nv_bfloat16 h0, l0, h1, l1;
                split2(p0, h0, l0); split2(p1, h1, l1);
                aPhi[nj >> 1][(nj & 1) * 2 + rr] = pack2(h0, h1);
                aPlo[nj >> 1][(nj & 1) * 2 + rr] = pack2(l0, l1);
            }
            rs += __shfl_xor_sync(0xffffffffu, rs, 1);
            rs += __shfl_xor_sync(0xffffffffu, rs, 2);
            float f = __expf(mi[rr] - mn);
            li[rr] = li[rr] * f + rs;
            mi[rr] = mn;
#pragma unroll
            for (int nj = 0; nj < 8; nj++) {
                o[nj][rr * 2] *= f;
                o[nj][rr * 2 + 1] *= f;
            }
        }

        // --- O += P V  (A from registers; k-blocks [Phi|Plo|Phi]) ---
        const uint32_t bVb = bKb + 25600 + stoff;
#pragma unroll
        for (int kk = 0; kk < 12; kk++) {
            const uint32_t* af = (kk < 4) ? aPhi[kk]
                               : (kk < 8) ? aPlo[kk - 4]
                                          : aPhi[kk - 8];
            uint32_t b[4][4];
#pragma unroll
            for (int j2 = 0; j2 < 4; j2++)
                ldsm4(b[j2], bVb + j2 * 16 * APITCH + kk * 32);
#pragma unroll
            for (int nj = 0; nj < 8; nj++)
                mma16816(o[nj], af, b[nj >> 1][nj & 1], b[nj >> 1][(nj & 1) + 2]);
        }
    }

    // --- epilogue: normalize, emit split layout for Wo GEMM ---
    const int b_ = bh >> 4, h_ = bh & 15;
#pragma unroll
    for (int rr = 0; rr < 2; rr++) {
        float inv = 1.f / li[rr];
        size_t base = ((size_t)b_ * SS + q0 + r1 + rr * 8) * (size_t)K3;
#pragma unroll
        for (int nj = 0; nj < 8; nj++) {
            int d = nj * 8 + 2 * q4;
            float v0 = o[nj][rr * 2] * inv, v1 = o[nj][rr * 2 + 1] * inv;
            __nv_bfloat16 h0, l0, h1, l1;
            split2(v0, h0, l0); split2(v1, h1, l1);
            uint2 pp; pp.x = pack2(h0, l0); pp.y = pack2(h1, l1);
            *(uint2*)&O[base + 2 * (h_ * 64 + d)] = pp;
            *(uint32_t*)&O[base + 2048 + h_ * 64 + d] = pack2(h0, h1);
        }
    }
}

// ---------------------------------------------------------------------------
extern "C" void kernel_launch(void* const* d_in, const int* in_sizes, int n_in,
                              void* d_out, int out_size) {
    const float* x  = (const float*)d_in[0];
    const float* Wq = (const float*)d_in[1];
    const float* bq = (const float*)d_in[2];
    const float* Wk = (const float*)d_in[3];
    const float* bk = (const float*)d_in[4];
    const float* Wv = (const float*)d_in[5];
    const float* bv = (const float*)d_in[6];
    const float* Wo = (const float*)d_in[7];
    const float* bo = (const float*)d_in[8];

    __nv_bfloat16 *xTb, *wqb, *wkb, *wvb, *wob, *qs, *ks, *vt, *attb;
    cudaGetSymbolAddress((void**)&xTb, g_xTbig);
    cudaGetSymbolAddress((void**)&wqb, g_Wqb);
    cudaGetSymbolAddress((void**)&wkb, g_Wkb);
    cudaGetSymbolAddress((void**)&wvb, g_Wvb);
    cudaGetSymbolAddress((void**)&wob, g_Wob);
    cudaGetSymbolAddress((void**)&qs, g_Qs);
    cudaGetSymbolAddress((void**)&ks, g_Ks);
    cudaGetSymbolAddress((void**)&vt, g_Vt);
    cudaGetSymbolAddress((void**)&attb, g_attbig);

    pe_transpose_split<<<dim3(SS / 32, DM / 32, BB), dim3(32, 32)>>>(x, xTb);
    wsplit_kernel<<<dim3(DM * DM / 256, 4), 256>>>(Wq, Wk, Wv, Wo, wqb, wkb, wvb, wob);

    cudaFuncSetAttribute(hmma_gemm, cudaFuncAttributeMaxDynamicSharedMemorySize, GEMM_SMEM);
    dim3 gg(DM / 128, (BB * SS) / 128);  // (8, 64)
    hmma_gemm<<<gg, 256, GEMM_SMEM>>>(xTb, wqb, bq, qs, 0);
    hmma_gemm<<<gg, 256, GEMM_SMEM>>>(xTb, wkb, bk, ks, 1);
    hmma_gemm<<<gg, 256, GEMM_SMEM>>>(xTb, wvb, bv, vt, 2);

    cudaFuncSetAttribute(attn_hmma, cudaFuncAttributeMaxDynamicSharedMemorySize, ATTN_SMEM);
    attn_hmma<<<dim3(SS / 128, BB * HH), 256, ATTN_SMEM>>>(qs, ks, vt, attb);

    hmma_gemm<<<gg, 256, GEMM_SMEM>>>(attb, wob, bo, d_out, 3);
}